// round 7
// baseline (speedup 1.0000x reference)
#include <cuda_runtime.h>
#include <cuda_fp16.h>
#include <cstdint>

// Problem constants
#define HEADS   6
#define HD      32      // head_dim
#define DIMM    192
#define NWIN    256     // tokens per 16x16 window
#define KS_STRIDE 40    // half elements per K row in smem (padded, conflict-free)
#define VT_STRIDE 264   // half elements per Vt row in smem (padded, conflict-free)
#define LOG2E   1.4426950408889634f
#define QK_SCALE 0.17677669529663687f   // 32^-0.5

__device__ __forceinline__ float ex2f(float x) {
    float y;
    asm("ex2.approx.f32 %0, %1;" : "=f"(y) : "f"(x));
    return y;
}

// pack two floats into f16x2 register: lo = first arg
__device__ __forceinline__ uint32_t pack_h2(float lo, float hi) {
    uint32_t r;
    // cvt.rn.f16x2.f32 d, a, b  ->  d.hi = cvt(a), d.lo = cvt(b)
    asm("cvt.rn.f16x2.f32 %0, %1, %2;" : "=r"(r) : "f"(hi), "f"(lo));
    return r;
}

// D += A * B   (m16n8k16, f16 inputs, f32 accumulate)
#define MMA(c, a, bb)                                                         \
    asm volatile(                                                             \
        "mma.sync.aligned.m16n8k16.row.col.f32.f16.f16.f32 "                  \
        "{%0,%1,%2,%3}, {%4,%5,%6,%7}, {%8,%9}, {%0,%1,%2,%3};"               \
        : "+f"((c)[0]), "+f"((c)[1]), "+f"((c)[2]), "+f"((c)[3])              \
        : "r"((a)[0]), "r"((a)[1]), "r"((a)[2]), "r"((a)[3]),                 \
          "r"((bb)[0]), "r"((bb)[1]))

__global__ __launch_bounds__(256, 2)
void winattn_kernel(const float* __restrict__ qkv,
                    const float* __restrict__ bias_table,
                    float* __restrict__ out)
{
    __shared__ half  Ks[NWIN * KS_STRIDE];   // K tile, row-major (n, k), fp16
    __shared__ half  Vt[HD * VT_STRIDE];     // V transposed: Vt[d][j] = V[j][d]
    __shared__ float bias_s[961];            // bias_table[:, head] * log2e

    const int tid  = threadIdx.x;
    const int bid  = blockIdx.x;
    const int head = bid % HEADS;
    const int win  = (bid / HEADS) & 255;
    const int b    = bid / (HEADS * 256);

    const int wh0 = (win >> 4) << 4;   // window top row in the image
    const int ww0 = (win & 15) << 4;   // window left col

    const long long plane = 65536LL * DIMM;

    // ---------------- load K, V into smem (fp16), bias column -------------
    {
        const float* kbase = qkv + (2 + b) * plane + head * HD;
        const float* vbase = qkv + (4 + b) * plane + head * HD;
        for (int vi = tid; vi < NWIN * (HD / 4); vi += 256) {
            const int p  = vi >> 3;            // window pixel 0..255
            const int c4 = (vi & 7) * 4;       // channel 0,4,...,28
            const int grow = (wh0 + (p >> 4)) * 256 + ww0 + (p & 15);
            const float4 kv = *(const float4*)(kbase + (long long)grow * DIMM + c4);
            const float4 vv = *(const float4*)(vbase + (long long)grow * DIMM + c4);
            *(half2*)&Ks[p * KS_STRIDE + c4]     = __floats2half2_rn(kv.x, kv.y);
            *(half2*)&Ks[p * KS_STRIDE + c4 + 2] = __floats2half2_rn(kv.z, kv.w);
            Vt[(c4 + 0) * VT_STRIDE + p] = __float2half_rn(vv.x);
            Vt[(c4 + 1) * VT_STRIDE + p] = __float2half_rn(vv.y);
            Vt[(c4 + 2) * VT_STRIDE + p] = __float2half_rn(vv.z);
            Vt[(c4 + 3) * VT_STRIDE + p] = __float2half_rn(vv.w);
        }
        for (int i = tid; i < 961; i += 256)
            bias_s[i] = bias_table[i * HEADS + head] * LOG2E;
    }

    // ---------------- per-warp Q fragments (loaded once, from GMEM) -------
    const int warp = tid >> 5;
    const int lane = tid & 31;
    const int g = lane >> 2;     // groupID 0..7
    const int t = lane & 3;      // thread-in-group
    const int mbase = warp * 32; // this warp's 32 query rows

    uint32_t af[2][2][4];        // [mtile][kstep][4 regs], Q * scale * log2e
    int ar[2][2];                // bias row codes for rows (g) and (g+8)
    {
        const float* qbase = qkv + b * plane + head * HD;
        const float qs = QK_SCALE * LOG2E;
        #pragma unroll
        for (int mt = 0; mt < 2; mt++) {
            const int rA = mbase + mt * 16 + g;
            const int rB = rA + 8;
            ar[mt][0] = ((rA >> 4) + 15) * 31 + (rA & 15) + 15;
            ar[mt][1] = ((rB >> 4) + 15) * 31 + (rB & 15) + 15;
            const int gA = (wh0 + (rA >> 4)) * 256 + ww0 + (rA & 15);
            const int gB = (wh0 + (rB >> 4)) * 256 + ww0 + (rB & 15);
            const float* qA = qbase + (long long)gA * DIMM;
            const float* qB = qbase + (long long)gB * DIMM;
            #pragma unroll
            for (int ks = 0; ks < 2; ks++) {
                const int c0 = ks * 16 + 2 * t;
                float2 f;
                f = *(const float2*)(qA + c0);
                af[mt][ks][0] = pack_h2(f.x * qs, f.y * qs);
                f = *(const float2*)(qB + c0);
                af[mt][ks][1] = pack_h2(f.x * qs, f.y * qs);
                f = *(const float2*)(qA + c0 + 8);
                af[mt][ks][2] = pack_h2(f.x * qs, f.y * qs);
                f = *(const float2*)(qB + c0 + 8);
                af[mt][ks][3] = pack_h2(f.x * qs, f.y * qs);
            }
        }
    }

    __syncthreads();

    // ---------------- main loop over 16-column K blocks -------------------
    float o[2][4][4] = {};   // [mtile][d-tile][4] fp32 accumulators
    float rs[2][2]   = {};   // row sums: [mtile][row-half]

    #pragma unroll 1
    for (int j0 = 0; j0 < NWIN; j0 += 16) {
        // B fragments of K for this block: [ntile][kstep][2]
        uint32_t bf[2][2][2];
        #pragma unroll
        for (int nt = 0; nt < 2; nt++) {
            const int row = j0 + nt * 8 + g;
            #pragma unroll
            for (int ks = 0; ks < 2; ks++) {
                bf[nt][ks][0] = *(const uint32_t*)&Ks[row * KS_STRIDE + ks * 16 + 2 * t];
                bf[nt][ks][1] = *(const uint32_t*)&Ks[row * KS_STRIDE + ks * 16 + 8 + 2 * t];
            }
        }

        // S = Q K^T   (scaled, in log2 units)
        float s[2][2][4] = {};
        #pragma unroll
        for (int mt = 0; mt < 2; mt++)
            #pragma unroll
            for (int nt = 0; nt < 2; nt++)
                #pragma unroll
                for (int ks = 0; ks < 2; ks++)
                    MMA(s[mt][nt], af[mt][ks], bf[nt][ks]);

        // bias column codes for this block
        int bc[2][2];
        #pragma unroll
        for (int nt = 0; nt < 2; nt++) {
            const int cA = j0 + nt * 8 + 2 * t;
            const int cB = cA + 1;
            bc[nt][0] = (cA >> 4) * 31 + (cA & 15);
            bc[nt][1] = (cB >> 4) * 31 + (cB & 15);
        }

        // P = 2^(S + bias), packed straight into A-fragments for PV
        uint32_t pa[2][4];
        #pragma unroll
        for (int mt = 0; mt < 2; mt++) {
            #pragma unroll
            for (int nt = 0; nt < 2; nt++) {
                const float p0 = ex2f(s[mt][nt][0] + bias_s[ar[mt][0] - bc[nt][0]]);
                const float p1 = ex2f(s[mt][nt][1] + bias_s[ar[mt][0] - bc[nt][1]]);
                const float p2 = ex2f(s[mt][nt][2] + bias_s[ar[mt][1] - bc[nt][0]]);
                const float p3 = ex2f(s[mt][nt][3] + bias_s[ar[mt][1] - bc[nt][1]]);
                rs[mt][0] += p0 + p1;
                rs[mt][1] += p2 + p3;
                pa[mt][nt * 2 + 0] = pack_h2(p0, p1);
                pa[mt][nt * 2 + 1] = pack_h2(p2, p3);
            }
        }

        // O += P * V   (B fragments from Vt, shared across mtiles)
        uint32_t bv[4][2];
        #pragma unroll
        for (int dt = 0; dt < 4; dt++) {
            bv[dt][0] = *(const uint32_t*)&Vt[(dt * 8 + g) * VT_STRIDE + j0 + 2 * t];
            bv[dt][1] = *(const uint32_t*)&Vt[(dt * 8 + g) * VT_STRIDE + j0 + 8 + 2 * t];
        }
        #pragma unroll
        for (int mt = 0; mt < 2; mt++)
            #pragma unroll
            for (int dt = 0; dt < 4; dt++)
                MMA(o[mt][dt], pa[mt], bv[dt]);
    }

    // ---------------- normalize and write output --------------------------
    #pragma unroll
    for (int mt = 0; mt < 2; mt++) {
        float r0 = rs[mt][0], r1 = rs[mt][1];
        r0 += __shfl_xor_sync(0xFFFFFFFFu, r0, 1);
        r0 += __shfl_xor_sync(0xFFFFFFFFu, r0, 2);
        r1 += __shfl_xor_sync(0xFFFFFFFFu, r1, 1);
        r1 += __shfl_xor_sync(0xFFFFFFFFu, r1, 2);
        const float inv0 = 1.0f / r0;
        const float inv1 = 1.0f / r1;

        const int rA = mbase + mt * 16 + g;
        const int rB = rA + 8;
        const long long gA = b * 65536LL + (wh0 + (rA >> 4)) * 256 + ww0 + (rA & 15);
        const long long gB = b * 65536LL + (wh0 + (rB >> 4)) * 256 + ww0 + (rB & 15);
        float* oA = out + gA * DIMM + head * HD;
        float* oB = out + gB * DIMM + head * HD;
        #pragma unroll
        for (int dt = 0; dt < 4; dt++) {
            const int d = dt * 8 + 2 * t;
            *(float2*)(oA + d) = make_float2(o[mt][dt][0] * inv0, o[mt][dt][1] * inv0);
            *(float2*)(oB + d) = make_float2(o[mt][dt][2] * inv1, o[mt][dt][3] * inv1);
        }
    }
}

extern "C" void kernel_launch(void* const* d_in, const int* in_sizes, int n_in,
                              void* d_out, int out_size)
{
    (void)in_sizes; (void)n_in; (void)out_size;
    const float* qkv        = (const float*)d_in[0];
    const float* bias_table = (const float*)d_in[1];
    float* out              = (float*)d_out;

    // 2 batches * 256 windows * 6 heads = 3072 CTAs, 256 threads each
    winattn_kernel<<<3072, 256>>>(qkv, bias_table, out);
}

// round 8
// speedup vs baseline: 1.2267x; 1.2267x over previous
#include <cuda_runtime.h>
#include <cuda_fp16.h>
#include <cstdint>

// Problem constants
#define HEADS   6
#define HD      32      // head_dim
#define DIMM    192
#define NWIN    256     // tokens per 16x16 window
#define KS_STRIDE 40    // half elements per K row in smem (80B rows, conflict-free for ldmatrix)
#define VT_STRIDE 264   // half elements per Vt row in smem (528B rows, conflict-free)
#define LOG2E   1.4426950408889634f
#define QK_SCALE 0.17677669529663687f   // 32^-0.5

__device__ __forceinline__ float ex2f(float x) {
    float y;
    asm("ex2.approx.f32 %0, %1;" : "=f"(y) : "f"(x));
    return y;
}

// pack two floats into f16x2 register: lo = first arg
__device__ __forceinline__ uint32_t pack_h2(float lo, float hi) {
    uint32_t r;
    asm("cvt.rn.f16x2.f32 %0, %1, %2;" : "=r"(r) : "f"(hi), "f"(lo));
    return r;
}

__device__ __forceinline__ uint32_t smem_u32(const void* p) {
    uint32_t a;
    asm("{ .reg .u64 t; cvta.to.shared.u64 t, %1; cvt.u32.u64 %0, t; }"
        : "=r"(a) : "l"(p));
    return a;
}

__device__ __forceinline__ void ldsm4(uint32_t* r, uint32_t addr) {
    asm volatile("ldmatrix.sync.aligned.m8n8.x4.shared.b16 {%0,%1,%2,%3}, [%4];"
        : "=r"(r[0]), "=r"(r[1]), "=r"(r[2]), "=r"(r[3]) : "r"(addr));
}

// D += A * B   (m16n8k16, f16 inputs, f32 accumulate)
#define MMA(c, a, bb)                                                         \
    asm volatile(                                                             \
        "mma.sync.aligned.m16n8k16.row.col.f32.f16.f16.f32 "                  \
        "{%0,%1,%2,%3}, {%4,%5,%6,%7}, {%8,%9}, {%0,%1,%2,%3};"               \
        : "+f"((c)[0]), "+f"((c)[1]), "+f"((c)[2]), "+f"((c)[3])              \
        : "r"((a)[0]), "r"((a)[1]), "r"((a)[2]), "r"((a)[3]),                 \
          "r"((bb)[0]), "r"((bb)[1]))

__global__ __launch_bounds__(512, 2)
void winattn_kernel(const float* __restrict__ qkv,
                    const float* __restrict__ bias_table,
                    float* __restrict__ out)
{
    __shared__ half  Ks[NWIN * KS_STRIDE];   // K tile, row-major (n, k), fp16
    __shared__ half  Vt[HD * VT_STRIDE];     // V transposed: Vt[d][j] = V[j][d]
    __shared__ float bias_s[961];            // bias_table[:, head] * log2e

    const int tid  = threadIdx.x;
    const int bid  = blockIdx.x;
    const int head = bid % HEADS;
    const int win  = (bid / HEADS) & 255;
    const int b    = bid / (HEADS * 256);

    const int wh0 = (win >> 4) << 4;   // window top row in the image
    const int ww0 = (win & 15) << 4;   // window left col

    const long long plane = 65536LL * DIMM;

    // ---------------- load K, V into smem (fp16), bias column -------------
    {
        const float* kbase = qkv + (2 + b) * plane + head * HD;
        const float* vbase = qkv + (4 + b) * plane + head * HD;
        for (int vi = tid; vi < NWIN * (HD / 4); vi += 512) {
            const int p  = vi >> 3;            // window pixel 0..255
            const int c4 = (vi & 7) * 4;       // channel 0,4,...,28
            const int grow = (wh0 + (p >> 4)) * 256 + ww0 + (p & 15);
            const float4 kv = *(const float4*)(kbase + (long long)grow * DIMM + c4);
            const float4 vv = *(const float4*)(vbase + (long long)grow * DIMM + c4);
            *(half2*)&Ks[p * KS_STRIDE + c4]     = __floats2half2_rn(kv.x, kv.y);
            *(half2*)&Ks[p * KS_STRIDE + c4 + 2] = __floats2half2_rn(kv.z, kv.w);
            Vt[(c4 + 0) * VT_STRIDE + p] = __float2half_rn(vv.x);
            Vt[(c4 + 1) * VT_STRIDE + p] = __float2half_rn(vv.y);
            Vt[(c4 + 2) * VT_STRIDE + p] = __float2half_rn(vv.z);
            Vt[(c4 + 3) * VT_STRIDE + p] = __float2half_rn(vv.w);
        }
        for (int i = tid; i < 961; i += 512)
            bias_s[i] = bias_table[i * HEADS + head] * LOG2E;
    }

    // ---------------- per-warp Q fragments (16 rows per warp) -------------
    const int warp  = tid >> 5;
    const int lane  = tid & 31;
    const int g     = lane >> 2;     // groupID 0..7
    const int t     = lane & 3;      // thread-in-group
    const int wbase = warp * 16;     // this warp's 16 query rows

    uint32_t af[2][4];               // [kstep][4 regs], Q * scale * log2e
    int ar0, ar1;                    // bias row codes for rows rA, rB
    {
        const float* qbase = qkv + b * plane + head * HD;
        const float qs = QK_SCALE * LOG2E;
        const int rA = wbase + g;
        const int rB = rA + 8;
        ar0 = ((rA >> 4) + 15) * 31 + (rA & 15) + 15;
        ar1 = ((rB >> 4) + 15) * 31 + (rB & 15) + 15;
        const int gA = (wh0 + (rA >> 4)) * 256 + ww0 + (rA & 15);
        const int gB = (wh0 + (rB >> 4)) * 256 + ww0 + (rB & 15);
        const float* qA = qbase + (long long)gA * DIMM;
        const float* qB = qbase + (long long)gB * DIMM;
        #pragma unroll
        for (int ks = 0; ks < 2; ks++) {
            const int c0 = ks * 16 + 2 * t;
            float2 f;
            f = *(const float2*)(qA + c0);
            af[ks][0] = pack_h2(f.x * qs, f.y * qs);
            f = *(const float2*)(qB + c0);
            af[ks][1] = pack_h2(f.x * qs, f.y * qs);
            f = *(const float2*)(qA + c0 + 8);
            af[ks][2] = pack_h2(f.x * qs, f.y * qs);
            f = *(const float2*)(qB + c0 + 8);
            af[ks][3] = pack_h2(f.x * qs, f.y * qs);
        }
    }

    __syncthreads();

    // ---------------- ldmatrix base addresses (incremented per iter) ------
    // Each ldmatrix.x4: lane l addresses matrix m = l>>3, row r = l&7.
    const int lm = lane >> 3;   // matrix id
    const int lr = lane & 7;    // row within matrix
    // K tiles per call (one call per ks): m = (nt<<1)|khalf
    //   row = j0 + nt*8 + lr, col halves khalf*8 (+ks*16 as +32B offset)
    uint32_t kaddr = smem_u32(&Ks[((lm >> 1) * 8 + lr) * KS_STRIDE + (lm & 1) * 8]);
    // V tiles: m = (dt<<1)|jhalf : row d = dt*8 + lr, col j0 + jhalf*8
    uint32_t vaddr = smem_u32(&Vt[((lm >> 1) * 8 + lr) * VT_STRIDE + (lm & 1) * 8]);
    const uint32_t voff2 = 16 * VT_STRIDE * 2;   // second call: dt += 2

    // bias column codes (incremental: += 31 each 16-col block)
    int b00 = 2 * t;          // col = j0 + 2t
    int b01 = 2 * t + 1;      // col = j0 + 2t + 1

    float o[4][4] = {};       // [d-tile][4] fp32 accumulators
    float rs0 = 0.f, rs1 = 0.f;

    // ---------------- main loop over 16-column K blocks -------------------
    #pragma unroll 1
    for (int j0 = 0; j0 < NWIN; j0 += 16) {
        // K fragments: bf[ks] = {nt0.b0, nt0.b1, nt1.b0, nt1.b1}
        uint32_t bf[2][4];
        ldsm4(bf[0], kaddr);
        ldsm4(bf[1], kaddr + 32);

        // S = Q K^T (scaled, log2 units)
        float s[2][4] = {};
        MMA(s[0], af[0], &bf[0][0]);
        MMA(s[0], af[1], &bf[1][0]);
        MMA(s[1], af[0], &bf[0][2]);
        MMA(s[1], af[1], &bf[1][2]);

        // P = 2^(S + bias), packed straight into the PV A-fragment
        uint32_t pa[4];
        #pragma unroll
        for (int nt = 0; nt < 2; nt++) {
            const int c0 = b00 + nt * 8;
            const int c1 = b01 + nt * 8;
            const float p0 = ex2f(s[nt][0] + bias_s[ar0 - c0]);
            const float p1 = ex2f(s[nt][1] + bias_s[ar0 - c1]);
            const float p2 = ex2f(s[nt][2] + bias_s[ar1 - c0]);
            const float p3 = ex2f(s[nt][3] + bias_s[ar1 - c1]);
            rs0 += p0 + p1;
            rs1 += p2 + p3;
            pa[nt * 2 + 0] = pack_h2(p0, p1);
            pa[nt * 2 + 1] = pack_h2(p2, p3);
        }

        // V fragments: bv = {dt0.b0, dt0.b1, dt1.b0, dt1.b1, dt2.., dt3..}
        uint32_t bv[8];
        ldsm4(bv,     vaddr);
        ldsm4(bv + 4, vaddr + voff2);

        // O += P * V
        MMA(o[0], pa, &bv[0]);
        MMA(o[1], pa, &bv[2]);
        MMA(o[2], pa, &bv[4]);
        MMA(o[3], pa, &bv[6]);

        kaddr += 16 * KS_STRIDE * 2;   // next 16 K rows
        vaddr += 32;                   // next 16 j columns (16 halves)
        b00 += 31;
        b01 += 31;
    }

    // ---------------- normalize and write output --------------------------
    rs0 += __shfl_xor_sync(0xFFFFFFFFu, rs0, 1);
    rs0 += __shfl_xor_sync(0xFFFFFFFFu, rs0, 2);
    rs1 += __shfl_xor_sync(0xFFFFFFFFu, rs1, 1);
    rs1 += __shfl_xor_sync(0xFFFFFFFFu, rs1, 2);
    const float inv0 = 1.0f / rs0;
    const float inv1 = 1.0f / rs1;

    const int rA = wbase + g;
    const int rB = rA + 8;
    const long long gA = b * 65536LL + (wh0 + (rA >> 4)) * 256 + ww0 + (rA & 15);
    const long long gB = b * 65536LL + (wh0 + (rB >> 4)) * 256 + ww0 + (rB & 15);
    float* oA = out + gA * DIMM + head * HD;
    float* oB = out + gB * DIMM + head * HD;
    #pragma unroll
    for (int dt = 0; dt < 4; dt++) {
        const int d = dt * 8 + 2 * t;
        *(float2*)(oA + d) = make_float2(o[dt][0] * inv0, o[dt][1] * inv0);
        *(float2*)(oB + d) = make_float2(o[dt][2] * inv1, o[dt][3] * inv1);
    }
}

extern "C" void kernel_launch(void* const* d_in, const int* in_sizes, int n_in,
                              void* d_out, int out_size)
{
    (void)in_sizes; (void)n_in; (void)out_size;
    const float* qkv        = (const float*)d_in[0];
    const float* bias_table = (const float*)d_in[1];
    float* out              = (float*)d_out;

    // 2 batches * 256 windows * 6 heads = 3072 CTAs, 512 threads each
    winattn_kernel<<<3072, 512>>>(qkv, bias_table, out);
}

// round 9
// speedup vs baseline: 1.2626x; 1.0293x over previous
#include <cuda_runtime.h>
#include <cuda_fp16.h>
#include <cstdint>

// Problem constants
#define HEADS   6
#define HD      32      // head_dim
#define DIMM    192
#define NWIN    256     // tokens per 16x16 window
#define KS_STRIDE 40    // half elements per K row in smem (80B rows, conflict-free)
#define VT_STRIDE 264   // half elements per Vt row in smem (528B rows, conflict-free)
#define LOG2E   1.4426950408889634f
#define QK_SCALE 0.17677669529663687f   // 32^-0.5

__device__ __forceinline__ float ex2f(float x) {
    float y;
    asm("ex2.approx.f32 %0, %1;" : "=f"(y) : "f"(x));
    return y;
}
__device__ __forceinline__ float rcpf(float x) {
    float y;
    asm("rcp.approx.f32 %0, %1;" : "=f"(y) : "f"(x));
    return y;
}

// pack two floats into f16x2 register: lo = first arg
__device__ __forceinline__ uint32_t pack_h2(float lo, float hi) {
    uint32_t r;
    asm("cvt.rn.f16x2.f32 %0, %1, %2;" : "=r"(r) : "f"(hi), "f"(lo));
    return r;
}

__device__ __forceinline__ uint32_t smem_u32(const void* p) {
    uint32_t a;
    asm("{ .reg .u64 t; cvta.to.shared.u64 t, %1; cvt.u32.u64 %0, t; }"
        : "=r"(a) : "l"(p));
    return a;
}

__device__ __forceinline__ void ldsm4(uint32_t* r, uint32_t addr) {
    asm volatile("ldmatrix.sync.aligned.m8n8.x4.shared.b16 {%0,%1,%2,%3}, [%4];"
        : "=r"(r[0]), "=r"(r[1]), "=r"(r[2]), "=r"(r[3]) : "r"(addr));
}

// D += A * B   (m16n8k16, f16 inputs, f32 accumulate) — NON-volatile: pure
// register op, lets ptxas interleave MMAs with loads / MUFU.
#define MMA(c, a, bb)                                                         \
    asm("mma.sync.aligned.m16n8k16.row.col.f32.f16.f16.f32 "                  \
        "{%0,%1,%2,%3}, {%4,%5,%6,%7}, {%8,%9}, {%0,%1,%2,%3};"               \
        : "+f"((c)[0]), "+f"((c)[1]), "+f"((c)[2]), "+f"((c)[3])              \
        : "r"((a)[0]), "r"((a)[1]), "r"((a)[2]), "r"((a)[3]),                 \
          "r"((bb)[0]), "r"((bb)[1]))

__global__ __launch_bounds__(512, 2)
void winattn_kernel(const float* __restrict__ qkv,
                    const float* __restrict__ bias_table,
                    float* __restrict__ out)
{
    __shared__ half   Ks[NWIN * KS_STRIDE];   // K tile, row-major (n, k), fp16
    __shared__ half   Vt[HD * VT_STRIDE];     // V transposed: Vt[d][j] = V[j][d]
    __shared__ float2 bias2[961];             // pair table: (b[i], b[i+1]) * log2e

    const int tid  = threadIdx.x;
    const int bid  = blockIdx.x;
    const int head = bid % HEADS;
    const int win  = (bid / HEADS) & 255;
    const int b    = bid / (HEADS * 256);

    const int wh0 = (win >> 4) << 4;   // window top row in the image
    const int ww0 = (win & 15) << 4;   // window left col

    const long long plane = 65536LL * DIMM;

    // ---------------- load K, V into smem (fp16), bias pair table ---------
    {
        const float* kbase = qkv + (2 + b) * plane + head * HD;
        const float* vbase = qkv + (4 + b) * plane + head * HD;
        for (int vi = tid; vi < NWIN * (HD / 4); vi += 512) {
            const int p  = vi >> 3;            // window pixel 0..255
            const int c4 = (vi & 7) * 4;       // channel 0,4,...,28
            const int grow = (wh0 + (p >> 4)) * 256 + ww0 + (p & 15);
            const float4 kv = *(const float4*)(kbase + (long long)grow * DIMM + c4);
            const float4 vv = *(const float4*)(vbase + (long long)grow * DIMM + c4);
            *(half2*)&Ks[p * KS_STRIDE + c4]     = __floats2half2_rn(kv.x, kv.y);
            *(half2*)&Ks[p * KS_STRIDE + c4 + 2] = __floats2half2_rn(kv.z, kv.w);
            Vt[(c4 + 0) * VT_STRIDE + p] = __float2half_rn(vv.x);
            Vt[(c4 + 1) * VT_STRIDE + p] = __float2half_rn(vv.y);
            Vt[(c4 + 2) * VT_STRIDE + p] = __float2half_rn(vv.z);
            Vt[(c4 + 3) * VT_STRIDE + p] = __float2half_rn(vv.w);
        }
        for (int i = tid; i < 961; i += 512) {
            const float lo = bias_table[i * HEADS + head] * LOG2E;
            const int   in = (i < 960) ? i + 1 : 960;
            const float hi = bias_table[in * HEADS + head] * LOG2E;
            bias2[i] = make_float2(lo, hi);
        }
    }

    // ---------------- per-warp Q fragments (16 rows per warp) -------------
    const int warp  = tid >> 5;
    const int lane  = tid & 31;
    const int g     = lane >> 2;     // groupID 0..7
    const int t     = lane & 3;      // thread-in-group
    const int wbase = warp * 16;     // this warp's 16 query rows

    uint32_t af[2][4];               // [kstep][4 regs], Q * scale * log2e
    int ar0;                         // bias row code for row rA (rB = +8)
    {
        const float* qbase = qkv + b * plane + head * HD;
        const float qs = QK_SCALE * LOG2E;
        const int rA = wbase + g;
        const int rB = rA + 8;
        ar0 = ((rA >> 4) + 15) * 31 + (rA & 15) + 15;
        const int gA = (wh0 + (rA >> 4)) * 256 + ww0 + (rA & 15);
        const int gB = (wh0 + (rB >> 4)) * 256 + ww0 + (rB & 15);
        const float* qA = qbase + (long long)gA * DIMM;
        const float* qB = qbase + (long long)gB * DIMM;
        #pragma unroll
        for (int ks = 0; ks < 2; ks++) {
            const int c0 = ks * 16 + 2 * t;
            float2 f;
            f = *(const float2*)(qA + c0);
            af[ks][0] = pack_h2(f.x * qs, f.y * qs);
            f = *(const float2*)(qB + c0);
            af[ks][1] = pack_h2(f.x * qs, f.y * qs);
            f = *(const float2*)(qA + c0 + 8);
            af[ks][2] = pack_h2(f.x * qs, f.y * qs);
            f = *(const float2*)(qB + c0 + 8);
            af[ks][3] = pack_h2(f.x * qs, f.y * qs);
        }
    }

    __syncthreads();

    // ---------------- ldmatrix base addresses (incremented per iter) ------
    const int lm = lane >> 3;   // matrix id within ldmatrix.x4
    const int lr = lane & 7;    // row within matrix
    uint32_t kaddr = smem_u32(&Ks[((lm >> 1) * 8 + lr) * KS_STRIDE + (lm & 1) * 8]);
    uint32_t vaddr = smem_u32(&Vt[((lm >> 1) * 8 + lr) * VT_STRIDE + (lm & 1) * 8]);
    const uint32_t voff2 = 16 * VT_STRIDE * 2;   // second V call: dt += 2

    // Bias pair-table index (see algebra in header note):
    //   i00 = ar0 - code(c1) for nt=0; the 4 needed pairs are
    //   bias2[i00+8] (rB,nt0), bias2[i00] (rA,nt0 AND rB,nt1), bias2[i00-8] (rA,nt1)
    int i00 = ar0 - (2 * t + 1);     // decrements by 31 each 16-col block

    float o[4][4] = {};       // [d-tile][4] fp32 accumulators
    float rs0 = 0.f, rs1 = 0.f;

    // ---------------- main loop over 16-column K blocks -------------------
    #pragma unroll 1
    for (int it = 0; it < 16; it++) {
        // K fragments
        uint32_t bf[2][4];
        ldsm4(bf[0], kaddr);
        ldsm4(bf[1], kaddr + 32);
        // V fragments — hoisted before the S/exp chain to hide LDS latency
        uint32_t bv[8];
        ldsm4(bv,     vaddr);
        ldsm4(bv + 4, vaddr + voff2);

        // bias pairs -> initialize S accumulators (bias folded into MMA C)
        const float2 fm = bias2[i00];
        const float2 fh = bias2[i00 + 8];
        const float2 fl = bias2[i00 - 8];
        float s0[4], s1[4];
        s0[0] = fm.y; s0[1] = fm.x; s0[2] = fh.y; s0[3] = fh.x;
        s1[0] = fl.y; s1[1] = fl.x; s1[2] = fm.y; s1[3] = fm.x;

        // S = Q K^T + bias   (log2 units)
        MMA(s0, af[0], &bf[0][0]);
        MMA(s0, af[1], &bf[1][0]);
        MMA(s1, af[0], &bf[0][2]);
        MMA(s1, af[1], &bf[1][2]);

        // P = 2^S, packed straight into the PV A-fragment
        uint32_t pa[4];
        {
            const float p0 = ex2f(s0[0]);
            const float p1 = ex2f(s0[1]);
            const float p2 = ex2f(s0[2]);
            const float p3 = ex2f(s0[3]);
            rs0 += p0 + p1;
            rs1 += p2 + p3;
            pa[0] = pack_h2(p0, p1);
            pa[1] = pack_h2(p2, p3);
        }
        {
            const float p0 = ex2f(s1[0]);
            const float p1 = ex2f(s1[1]);
            const float p2 = ex2f(s1[2]);
            const float p3 = ex2f(s1[3]);
            rs0 += p0 + p1;
            rs1 += p2 + p3;
            pa[2] = pack_h2(p0, p1);
            pa[3] = pack_h2(p2, p3);
        }

        // O += P * V
        MMA(o[0], pa, &bv[0]);
        MMA(o[1], pa, &bv[2]);
        MMA(o[2], pa, &bv[4]);
        MMA(o[3], pa, &bv[6]);

        kaddr += 16 * KS_STRIDE * 2;   // next 16 K rows
        vaddr += 32;                   // next 16 j columns
        i00   -= 31;
    }

    // ---------------- normalize and write output --------------------------
    rs0 += __shfl_xor_sync(0xFFFFFFFFu, rs0, 1);
    rs0 += __shfl_xor_sync(0xFFFFFFFFu, rs0, 2);
    rs1 += __shfl_xor_sync(0xFFFFFFFFu, rs1, 1);
    rs1 += __shfl_xor_sync(0xFFFFFFFFu, rs1, 2);
    const float inv0 = rcpf(rs0);
    const float inv1 = rcpf(rs1);

    const int rA = wbase + g;
    const int rB = rA + 8;
    const long long gA = b * 65536LL + (wh0 + (rA >> 4)) * 256 + ww0 + (rA & 15);
    const long long gB = b * 65536LL + (wh0 + (rB >> 4)) * 256 + ww0 + (rB & 15);
    float* oA = out + gA * DIMM + head * HD;
    float* oB = out + gB * DIMM + head * HD;
    #pragma unroll
    for (int dt = 0; dt < 4; dt++) {
        const int d = dt * 8 + 2 * t;
        *(float2*)(oA + d) = make_float2(o[dt][0] * inv0, o[dt][1] * inv0);
        *(float2*)(oB + d) = make_float2(o[dt][2] * inv1, o[dt][3] * inv1);
    }
}

extern "C" void kernel_launch(void* const* d_in, const int* in_sizes, int n_in,
                              void* d_out, int out_size)
{
    (void)in_sizes; (void)n_in; (void)out_size;
    const float* qkv        = (const float*)d_in[0];
    const float* bias_table = (const float*)d_in[1];
    float* out              = (float*)d_out;

    // 2 batches * 256 windows * 6 heads = 3072 CTAs, 512 threads each
    winattn_kernel<<<3072, 512>>>(qkv, bias_table, out);
}